// round 6
// baseline (speedup 1.0000x reference)
#include <cuda_runtime.h>
#include <cuda_fp16.h>

// Fixed shapes: N=10000 nodes, E=320000 edges, node_dim=out_dim=128, init_dim=257.
#define DIM 128
#define MAX_N 10016
#define NEG_SLOPE 0.01f

// Static scratch (no allocation allowed)
__device__ __half g_P1h[MAX_N * DIM];   // fp16: atom @ (W1a+W2)^T
__device__ __half g_P2h[MAX_N * DIM];   // fp16: atom @ (W1b+W2)^T
// Combined weights in mma.sync m16n8k16 B-fragment layout (fp16):
//   index = ((kt*16 + nt)*32 + lane)*4 + slot
__device__ __half g_WAf[8 * 16 * 32 * 4];   // W1a + W2   (32 KB)
__device__ __half g_WBf[8 * 16 * 32 * 4];   // W1b + W2   (32 KB)
__device__ float  g_wc[DIM];                // W1[:,256]
__device__ float  g_bias[DIM];              // b1 + b2

__device__ __forceinline__ void pdl_trigger() {
    asm volatile("griddepcontrol.launch_dependents;" ::: "memory");
}
__device__ __forceinline__ void pdl_wait() {
    asm volatile("griddepcontrol.wait;" ::: "memory");
}

// ---------------------------------------------------------------------------
// Kernel 0: combine weights + emit fp16 B-fragments. block = o, thread = k.
// ---------------------------------------------------------------------------
__global__ void prep_weights(const float* __restrict__ W1,
                             const float* __restrict__ b1,
                             const float* __restrict__ W2,
                             const float* __restrict__ b2) {
    pdl_trigger();   // let node_mma start its A-tile fill immediately
    const int o = blockIdx.x;    // output col n, 0..127
    const int k = threadIdx.x;   // input feature, 0..127
    const float w2 = W2[o * DIM + k];
    const float wa = W1[o * 257 + k]       + w2;
    const float wb = W1[o * 257 + DIM + k] + w2;

    const int kt   = k >> 4;
    const int r    = k & 15;
    const int tig  = (r & 7) >> 1;
    const int lane = (o & 7) * 4 + tig;
    const int slot = ((r >= 8) ? 2 : 0) + (r & 1);
    const int nt   = o >> 3;
    const int idx  = ((kt * 16 + nt) * 32 + lane) * 4 + slot;
    g_WAf[idx] = __float2half_rn(wa);
    g_WBf[idx] = __float2half_rn(wb);

    if (k == 0) {
        g_wc[o]   = W1[o * 257 + 256];
        g_bias[o] = b1[o] + b2[o];
    }
}

// ---------------------------------------------------------------------------
// Kernel 1: node projections on tensor cores, m32 tiles (2x m16 per block).
// 128 threads / 4 warps; warp w owns n in [w*32, w*32+32). Every B fragment
// is reused across both m16 A-tiles (halves weight L2 traffic vs m16).
// ---------------------------------------------------------------------------
#define SA_STRIDE 136   // halves per row: conflict-free a-fragment LDS

__device__ __forceinline__ void mma16816(float* c, const unsigned* a, uint2 b) {
    asm volatile(
        "mma.sync.aligned.m16n8k16.row.col.f32.f16.f16.f32 "
        "{%0,%1,%2,%3}, {%4,%5,%6,%7}, {%8,%9}, {%0,%1,%2,%3};"
        : "+f"(c[0]), "+f"(c[1]), "+f"(c[2]), "+f"(c[3])
        : "r"(a[0]), "r"(a[1]), "r"(a[2]), "r"(a[3]), "r"(b.x), "r"(b.y));
}

__global__ void __launch_bounds__(128) node_mma(const float* __restrict__ atom, int N) {
    __shared__ __half sA[32 * SA_STRIDE];   // m32 x k128 fp16
    const int t    = threadIdx.x;
    const int base = blockIdx.x * 32;

    pdl_trigger();   // edge kernel may start loading indices now

    // Fill A tile BEFORE waiting on prep (independent of weights).
    // 256 segments of 16 cols; thread t does segments t and t+128.
    #pragma unroll
    for (int ss = 0; ss < 2; ss++) {
        const int seg = t + ss * 128;
        const int r  = seg >> 3;
        const int c0 = (seg & 7) * 16;
        const int n  = base + r;
        __half* dstp = &sA[r * SA_STRIDE + c0];
        if (n < N) {
            const float4* srcp = reinterpret_cast<const float4*>(atom + n * DIM + c0);
            #pragma unroll
            for (int i = 0; i < 4; i++) {
                const float4 v = srcp[i];
                reinterpret_cast<__half2*>(dstp)[2 * i]     = __floats2half2_rn(v.x, v.y);
                reinterpret_cast<__half2*>(dstp)[2 * i + 1] = __floats2half2_rn(v.z, v.w);
            }
        } else {
            #pragma unroll
            for (int i = 0; i < 8; i++)
                reinterpret_cast<__half2*>(dstp)[i] = __floats2half2_rn(0.f, 0.f);
        }
    }
    __syncthreads();

    pdl_wait();      // weights must be ready from here on

    const int lane = t & 31;
    const int w    = t >> 5;
    const int g    = lane >> 2;
    const int tig  = lane & 3;

    float c1[2][4][4], c2[2][4][4];
    #pragma unroll
    for (int tt = 0; tt < 2; tt++)
        #pragma unroll
        for (int j = 0; j < 4; j++)
            #pragma unroll
            for (int i = 0; i < 4; i++) { c1[tt][j][i] = 0.f; c2[tt][j][i] = 0.f; }

    const uint2* __restrict__ WA = reinterpret_cast<const uint2*>(g_WAf);
    const uint2* __restrict__ WB = reinterpret_cast<const uint2*>(g_WBf);

    #pragma unroll
    for (int kt = 0; kt < 8; kt++) {
        const int k0 = kt * 16 + tig * 2;
        unsigned a0[4], a1[4];
        a0[0] = *reinterpret_cast<const unsigned*>(&sA[g * SA_STRIDE + k0]);
        a0[1] = *reinterpret_cast<const unsigned*>(&sA[(g + 8) * SA_STRIDE + k0]);
        a0[2] = *reinterpret_cast<const unsigned*>(&sA[g * SA_STRIDE + k0 + 8]);
        a0[3] = *reinterpret_cast<const unsigned*>(&sA[(g + 8) * SA_STRIDE + k0 + 8]);
        a1[0] = *reinterpret_cast<const unsigned*>(&sA[(16 + g) * SA_STRIDE + k0]);
        a1[1] = *reinterpret_cast<const unsigned*>(&sA[(24 + g) * SA_STRIDE + k0]);
        a1[2] = *reinterpret_cast<const unsigned*>(&sA[(16 + g) * SA_STRIDE + k0 + 8]);
        a1[3] = *reinterpret_cast<const unsigned*>(&sA[(24 + g) * SA_STRIDE + k0 + 8]);

        #pragma unroll
        for (int j = 0; j < 4; j++) {
            const int nt   = w * 4 + j;
            const int fidx = (kt * 16 + nt) * 32 + lane;
            const uint2 bA = __ldg(&WA[fidx]);
            const uint2 bB = __ldg(&WB[fidx]);
            mma16816(c1[0][j], a0, bA);
            mma16816(c1[1][j], a1, bA);
            mma16816(c2[0][j], a0, bB);
            mma16816(c2[1][j], a1, bB);
        }
    }

    // Stores: grid covers exactly MAX_N rows; padding rows never gathered.
    #pragma unroll
    for (int tt = 0; tt < 2; tt++) {
        const int r0 = base + tt * 16 + g;
        const int r1 = r0 + 8;
        #pragma unroll
        for (int j = 0; j < 4; j++) {
            const int col = (w * 4 + j) * 8 + tig * 2;
            *reinterpret_cast<__half2*>(&g_P1h[r0 * DIM + col]) =
                __floats2half2_rn(c1[tt][j][0], c1[tt][j][1]);
            *reinterpret_cast<__half2*>(&g_P2h[r0 * DIM + col]) =
                __floats2half2_rn(c2[tt][j][0], c2[tt][j][1]);
            *reinterpret_cast<__half2*>(&g_P1h[r1 * DIM + col]) =
                __floats2half2_rn(c1[tt][j][2], c1[tt][j][3]);
            *reinterpret_cast<__half2*>(&g_P2h[r1 * DIM + col]) =
                __floats2half2_rn(c2[tt][j][2], c2[tt][j][3]);
        }
    }
}

// ---------------------------------------------------------------------------
// Kernel 2: edge gather (fp16) + add + leaky_relu -> f32 streaming stores.
// Index/bond loads issued before pdl_wait (overlap with node_mma).
// ---------------------------------------------------------------------------
#define EPW 4
__device__ __forceinline__ float lrelu(float x) {
    return x > 0.0f ? x : NEG_SLOPE * x;
}

__global__ void __launch_bounds__(256) edge_kernel(const float* __restrict__ bond,
                            const int* __restrict__ src,
                            const int* __restrict__ dst,
                            float* __restrict__ out, int E) {
    const int lane = threadIdx.x & 31;
    const int warp = threadIdx.x >> 5;
    const int wpb  = blockDim.x >> 5;
    const int e0   = (blockIdx.x * wpb + warp) * EPW;

    // Pre-wait phase: everything independent of prep/node results.
    int   s[EPW], d[EPW];
    float bw[EPW];
    int   cnt = 0;
    #pragma unroll
    for (int i = 0; i < EPW; i++) {
        const int e = e0 + i;
        if (e < E) {
            s[i]  = __ldg(src + e);
            d[i]  = __ldg(dst + e);
            bw[i] = __ldg(bond + e);
            cnt++;
        }
    }

    pdl_wait();   // P tables / wc / bias valid from here

    const float4 wc4 = reinterpret_cast<const float4*>(g_wc)[lane];
    const float4 bs4 = reinterpret_cast<const float4*>(g_bias)[lane];

    const uint2* __restrict__ P1 = reinterpret_cast<const uint2*>(g_P1h);
    const uint2* __restrict__ P2 = reinterpret_cast<const uint2*>(g_P2h);
    float4* __restrict__ O = reinterpret_cast<float4*>(out);

    #pragma unroll
    for (int i = 0; i < EPW; i++) {
        if (i >= cnt) return;
        uint2 pu = __ldg(&P1[s[i] * (DIM / 4) + lane]);
        uint2 qu = __ldg(&P2[d[i] * (DIM / 4) + lane]);
        const float2 pa = __half22float2(*reinterpret_cast<__half2*>(&pu.x));
        const float2 pb = __half22float2(*reinterpret_cast<__half2*>(&pu.y));
        const float2 qa = __half22float2(*reinterpret_cast<__half2*>(&qu.x));
        const float2 qb = __half22float2(*reinterpret_cast<__half2*>(&qu.y));

        float4 r;
        r.x = lrelu(pa.x + qa.x + fmaf(bw[i], wc4.x, bs4.x));
        r.y = lrelu(pa.y + qa.y + fmaf(bw[i], wc4.y, bs4.y));
        r.z = lrelu(pb.x + qb.x + fmaf(bw[i], wc4.z, bs4.z));
        r.w = lrelu(pb.y + qb.y + fmaf(bw[i], wc4.w, bs4.w));

        __stcs(&O[(e0 + i) * (DIM / 4) + lane], r);
    }
}

// ---------------------------------------------------------------------------
// Launcher. Inputs: 0 atom[N,128] 1 bond[E,1] 2 src[E] 3 dst[E]
//                   4 W1[128,257] 5 b1[128] 6 W2[128,128] 7 b2[128]
// Output: [E,128] f32
// ---------------------------------------------------------------------------
extern "C" void kernel_launch(void* const* d_in, const int* in_sizes, int n_in,
                              void* d_out, int out_size) {
    const float* atom = (const float*)d_in[0];
    const float* bond = (const float*)d_in[1];
    const int*   src  = (const int*)d_in[2];
    const int*   dst  = (const int*)d_in[3];
    const float* W1   = (const float*)d_in[4];
    const float* b1   = (const float*)d_in[5];
    const float* W2   = (const float*)d_in[6];
    const float* b2   = (const float*)d_in[7];
    float* out = (float*)d_out;

    const int N = in_sizes[0] / DIM;
    const int E = in_sizes[2];

    prep_weights<<<DIM, DIM>>>(W1, b1, W2, b2);

    // node_mma with programmatic dependent launch (overlap A-fill with prep)
    {
        cudaLaunchConfig_t cfg = {};
        cfg.gridDim  = dim3((unsigned)((N + 31) / 32));
        cfg.blockDim = dim3(128);
        cudaLaunchAttribute at[1];
        at[0].id = cudaLaunchAttributeProgrammaticStreamSerialization;
        at[0].val.programmaticStreamSerializationAllowed = 1;
        cfg.attrs = at;
        cfg.numAttrs = 1;
        cudaLaunchKernelEx(&cfg, node_mma, atom, N);
    }

    // edge kernel with PDL (overlap index loads with node_mma)
    {
        const int threads = 256;                          // 8 warps/block
        const int edges_per_block = (threads / 32) * EPW; // 32
        cudaLaunchConfig_t cfg = {};
        cfg.gridDim  = dim3((unsigned)((E + edges_per_block - 1) / edges_per_block));
        cfg.blockDim = dim3(threads);
        cudaLaunchAttribute at[1];
        at[0].id = cudaLaunchAttributeProgrammaticStreamSerialization;
        at[0].val.programmaticStreamSerializationAllowed = 1;
        cfg.attrs = at;
        cfg.numAttrs = 1;
        cudaLaunchKernelEx(&cfg, edge_kernel, bond, src, dst, out, E);
    }
}

// round 8
// speedup vs baseline: 1.0420x; 1.0420x over previous
#include <cuda_runtime.h>
#include <cuda_fp16.h>

// Fixed shapes: N=10000 nodes, E=320000 edges, node_dim=out_dim=128, init_dim=257.
#define DIM 128
#define MAX_N 10016
#define NEG_SLOPE 0.01f

// Static scratch (no allocation allowed)
__device__ __half g_P1h[MAX_N * DIM];   // fp16: atom @ (W1a+W2)^T
__device__ __half g_P2h[MAX_N * DIM];   // fp16: atom @ (W1b+W2)^T
// Combined weights in mma.sync m16n8k16 B-fragment layout (fp16):
//   index = ((kt*16 + nt)*32 + lane)*4 + slot
__device__ __half g_WAf[8 * 16 * 32 * 4];   // W1a + W2   (32 KB)
__device__ __half g_WBf[8 * 16 * 32 * 4];   // W1b + W2   (32 KB)
__device__ float  g_wc[DIM];                // W1[:,256]
__device__ float  g_bias[DIM];              // b1 + b2

__device__ __forceinline__ void pdl_trigger() {
    asm volatile("griddepcontrol.launch_dependents;" ::: "memory");
}
__device__ __forceinline__ void pdl_wait() {
    asm volatile("griddepcontrol.wait;" ::: "memory");
}

// ---------------------------------------------------------------------------
// Kernel 0: combine weights + emit fp16 B-fragments. block = o, thread = k.
// Triggers dependent launch immediately: node_mma's A-fill runs under us.
// ---------------------------------------------------------------------------
__global__ void prep_weights(const float* __restrict__ W1,
                             const float* __restrict__ b1,
                             const float* __restrict__ W2,
                             const float* __restrict__ b2) {
    pdl_trigger();
    const int o = blockIdx.x;    // output col n, 0..127
    const int k = threadIdx.x;   // input feature, 0..127
    const float w2 = W2[o * DIM + k];
    const float wa = W1[o * 257 + k]       + w2;
    const float wb = W1[o * 257 + DIM + k] + w2;

    const int kt   = k >> 4;
    const int r    = k & 15;
    const int tig  = (r & 7) >> 1;
    const int lane = (o & 7) * 4 + tig;
    const int slot = ((r >= 8) ? 2 : 0) + (r & 1);
    const int nt   = o >> 3;
    const int idx  = ((kt * 16 + nt) * 32 + lane) * 4 + slot;
    g_WAf[idx] = __float2half_rn(wa);
    g_WBf[idx] = __float2half_rn(wb);

    if (k == 0) {
        g_wc[o]   = W1[o * 257 + 256];
        g_bias[o] = b1[o] + b2[o];
    }
}

// ---------------------------------------------------------------------------
// Kernel 1: node projections on tensor cores (mma.sync m16n8k16 f16->f32).
// R5 configuration: one m16 row-tile per 128-thread block (measured best).
// A-fill happens before pdl_wait (independent of prep's weight output).
// ---------------------------------------------------------------------------
#define SA_STRIDE 136   // halves per row: conflict-free a-fragment LDS

__device__ __forceinline__ void mma16816(float* c, const unsigned* a, uint2 b) {
    asm volatile(
        "mma.sync.aligned.m16n8k16.row.col.f32.f16.f16.f32 "
        "{%0,%1,%2,%3}, {%4,%5,%6,%7}, {%8,%9}, {%0,%1,%2,%3};"
        : "+f"(c[0]), "+f"(c[1]), "+f"(c[2]), "+f"(c[3])
        : "r"(a[0]), "r"(a[1]), "r"(a[2]), "r"(a[3]), "r"(b.x), "r"(b.y));
}

__global__ void __launch_bounds__(128) node_mma(const float* __restrict__ atom, int N) {
    __shared__ __half sA[16 * SA_STRIDE];   // m16 x k128 fp16, padded rows
    const int t    = threadIdx.x;
    const int base = blockIdx.x * 16;

    // Fill A tile (independent of weights -> before pdl_wait).
    {
        const int r  = t >> 3;
        const int c0 = (t & 7) * 16;
        const int n  = base + r;
        __half* dstp = &sA[r * SA_STRIDE + c0];
        if (n < N) {
            const float4* srcp = reinterpret_cast<const float4*>(atom + n * DIM + c0);
            #pragma unroll
            for (int i = 0; i < 4; i++) {
                const float4 v = srcp[i];
                reinterpret_cast<__half2*>(dstp)[2 * i]     = __floats2half2_rn(v.x, v.y);
                reinterpret_cast<__half2*>(dstp)[2 * i + 1] = __floats2half2_rn(v.z, v.w);
            }
        } else {
            #pragma unroll
            for (int i = 0; i < 8; i++)
                reinterpret_cast<__half2*>(dstp)[i] = __floats2half2_rn(0.f, 0.f);
        }
    }
    __syncthreads();

    pdl_wait();   // weights (B fragments) valid from here

    const int lane = t & 31;
    const int w    = t >> 5;        // warp id -> n-slice
    const int g    = lane >> 2;     // row within m16
    const int tig  = lane & 3;

    float c1[4][4], c2[4][4];
    #pragma unroll
    for (int j = 0; j < 4; j++)
        #pragma unroll
        for (int i = 0; i < 4; i++) { c1[j][i] = 0.f; c2[j][i] = 0.f; }

    const uint2* __restrict__ WA = reinterpret_cast<const uint2*>(g_WAf);
    const uint2* __restrict__ WB = reinterpret_cast<const uint2*>(g_WBf);

    #pragma unroll
    for (int kt = 0; kt < 8; kt++) {
        const int k0 = kt * 16 + tig * 2;
        unsigned a[4];
        a[0] = *reinterpret_cast<const unsigned*>(&sA[g * SA_STRIDE + k0]);
        a[1] = *reinterpret_cast<const unsigned*>(&sA[(g + 8) * SA_STRIDE + k0]);
        a[2] = *reinterpret_cast<const unsigned*>(&sA[g * SA_STRIDE + k0 + 8]);
        a[3] = *reinterpret_cast<const unsigned*>(&sA[(g + 8) * SA_STRIDE + k0 + 8]);

        #pragma unroll
        for (int j = 0; j < 4; j++) {
            const int nt   = w * 4 + j;
            const int fidx = (kt * 16 + nt) * 32 + lane;
            const uint2 bA = __ldg(&WA[fidx]);
            const uint2 bB = __ldg(&WB[fidx]);
            mma16816(c1[j], a, bA);
            mma16816(c2[j], a, bB);
        }
    }

    const int r0 = base + g, r1 = base + g + 8;
    #pragma unroll
    for (int j = 0; j < 4; j++) {
        const int col = (w * 4 + j) * 8 + tig * 2;
        if (r0 < N) {
            *reinterpret_cast<__half2*>(&g_P1h[r0 * DIM + col]) = __floats2half2_rn(c1[j][0], c1[j][1]);
            *reinterpret_cast<__half2*>(&g_P2h[r0 * DIM + col]) = __floats2half2_rn(c2[j][0], c2[j][1]);
        }
        if (r1 < N) {
            *reinterpret_cast<__half2*>(&g_P1h[r1 * DIM + col]) = __floats2half2_rn(c1[j][2], c1[j][3]);
            *reinterpret_cast<__half2*>(&g_P2h[r1 * DIM + col]) = __floats2half2_rn(c2[j][2], c2[j][3]);
        }
    }
}

// ---------------------------------------------------------------------------
// Kernel 2: edge gather (fp16) + add + leaky_relu -> f32 streaming stores.
// (R3/R5 configuration: EPW=4, 256 threads, plain launch — measured best.)
// ---------------------------------------------------------------------------
#define EPW 4
__device__ __forceinline__ float lrelu(float x) {
    return x > 0.0f ? x : NEG_SLOPE * x;
}

__global__ void __launch_bounds__(256) edge_kernel(const float* __restrict__ bond,
                            const int* __restrict__ src,
                            const int* __restrict__ dst,
                            float* __restrict__ out, int E) {
    const int lane = threadIdx.x & 31;
    const int warp = threadIdx.x >> 5;
    const int wpb  = blockDim.x >> 5;

    const float4 wc4 = reinterpret_cast<const float4*>(g_wc)[lane];
    const float4 bs4 = reinterpret_cast<const float4*>(g_bias)[lane];

    const uint2* __restrict__ P1 = reinterpret_cast<const uint2*>(g_P1h);
    const uint2* __restrict__ P2 = reinterpret_cast<const uint2*>(g_P2h);
    float4* __restrict__ O = reinterpret_cast<float4*>(out);

    const int e0 = (blockIdx.x * wpb + warp) * EPW;

    #pragma unroll
    for (int i = 0; i < EPW; i++) {
        const int e = e0 + i;
        if (e >= E) return;
        const int s = __ldg(src + e);
        const int d = __ldg(dst + e);
        const float bw = __ldg(bond + e);

        uint2 pu = __ldg(&P1[s * (DIM / 4) + lane]);
        uint2 qu = __ldg(&P2[d * (DIM / 4) + lane]);
        const float2 pa = __half22float2(*reinterpret_cast<__half2*>(&pu.x));
        const float2 pb = __half22float2(*reinterpret_cast<__half2*>(&pu.y));
        const float2 qa = __half22float2(*reinterpret_cast<__half2*>(&qu.x));
        const float2 qb = __half22float2(*reinterpret_cast<__half2*>(&qu.y));

        float4 r;
        r.x = lrelu(pa.x + qa.x + fmaf(bw, wc4.x, bs4.x));
        r.y = lrelu(pa.y + qa.y + fmaf(bw, wc4.y, bs4.y));
        r.z = lrelu(pb.x + qb.x + fmaf(bw, wc4.z, bs4.z));
        r.w = lrelu(pb.y + qb.y + fmaf(bw, wc4.w, bs4.w));

        __stcs(&O[e * (DIM / 4) + lane], r);   // streaming: keep P tables in L2
    }
}

// ---------------------------------------------------------------------------
// Launcher. Inputs: 0 atom[N,128] 1 bond[E,1] 2 src[E] 3 dst[E]
//                   4 W1[128,257] 5 b1[128] 6 W2[128,128] 7 b2[128]
// Output: [E,128] f32
// ---------------------------------------------------------------------------
extern "C" void kernel_launch(void* const* d_in, const int* in_sizes, int n_in,
                              void* d_out, int out_size) {
    const float* atom = (const float*)d_in[0];
    const float* bond = (const float*)d_in[1];
    const int*   src  = (const int*)d_in[2];
    const int*   dst  = (const int*)d_in[3];
    const float* W1   = (const float*)d_in[4];
    const float* b1   = (const float*)d_in[5];
    const float* W2   = (const float*)d_in[6];
    const float* b2   = (const float*)d_in[7];
    float* out = (float*)d_out;

    const int N = in_sizes[0] / DIM;
    const int E = in_sizes[2];

    prep_weights<<<DIM, DIM>>>(W1, b1, W2, b2);

    // node_mma with programmatic dependent launch: A-fill overlaps prep.
    {
        cudaLaunchConfig_t cfg = {};
        cfg.gridDim  = dim3((unsigned)((N + 15) / 16));
        cfg.blockDim = dim3(128);
        cudaLaunchAttribute at[1];
        at[0].id = cudaLaunchAttributeProgrammaticStreamSerialization;
        at[0].val.programmaticStreamSerializationAllowed = 1;
        cfg.attrs = at;
        cfg.numAttrs = 1;
        cudaLaunchKernelEx(&cfg, node_mma, atom, N);
    }

    // edge kernel: plain launch (waits for node_mma via stream order).
    const int threads = 256;                          // 8 warps/block
    const int edges_per_block = (threads / 32) * EPW; // 32
    edge_kernel<<<(E + edges_per_block - 1) / edges_per_block, threads>>>(
        bond, src, dst, out, E);
}